// round 6
// baseline (speedup 1.0000x reference)
#include <cuda_runtime.h>
#include <cuda_bf16.h>
#include <math.h>
#include <cstdint>

// Problem constants
#define BB 32
#define HH 128
#define WW 128
#define CC 64
#define MY 16
#define NKX 32   // 16 positive kx + 16 negative kx (112..127)

// ---------------------------------------------------------------------------
// Scratch (static device globals — no allocations allowed)
// ---------------------------------------------------------------------------
__device__ __align__(16) __nv_bfloat16 g_P1b[BB * MY * 256 * CC];   // [b][ky][h*2+p][c]
__device__ __align__(16) __nv_bfloat16 g_X2 [NKX * MY * BB * 128];  // [kxi][ky][b][(c,q)]
__device__ __align__(16) __nv_bfloat16 g_Y2 [BB * MY * 64 * CC];    // [b][ky][(kxi,q)][c]
__device__ __align__(16) __nv_bfloat16 g_Z2 [BB * HH * CC * 32];    // [bh][c][p*16+ky]
__device__ __align__(16) __nv_bfloat16 g_W2 [512 * 128 * 128];      // [kq][(i,q)][(o,p)]
__device__ __align__(16) __nv_bfloat16 g_Hinv[256 * 64];            // [(h,p)][(kxi,q)]
__device__ __align__(16) __nv_bfloat16 g_F2 [32 * 128];             // [ky*2+p][w]
__device__ __align__(16) __nv_bfloat16 g_G2 [64 * 256];             // [kxi*2+p][h*2+q]
__device__ __align__(16) __nv_bfloat16 g_T  [WW * 32];              // [w][j] inverse-W DFT
__device__ __align__(16) __nv_bfloat16 g_Bk [CC * 128];             // [c][k]: K_hi|K_lo

// ---------------------------------------------------------------------------
// mma.sync helpers
// ---------------------------------------------------------------------------
__device__ __forceinline__ uint32_t smem_u32(const void* p) {
    uint32_t a;
    asm("{ .reg .u64 t; cvta.to.shared.u64 t, %1; cvt.u32.u64 %0, t; }" : "=r"(a) : "l"(p));
    return a;
}
#define LDSM4(r0, r1, r2, r3, addr) \
    asm volatile("ldmatrix.sync.aligned.m8n8.x4.shared.b16 {%0,%1,%2,%3}, [%4];" \
        : "=r"(r0), "=r"(r1), "=r"(r2), "=r"(r3) : "r"(addr))
#define LDSM4T(r0, r1, r2, r3, addr) \
    asm volatile("ldmatrix.sync.aligned.m8n8.x4.trans.shared.b16 {%0,%1,%2,%3}, [%4];" \
        : "=r"(r0), "=r"(r1), "=r"(r2), "=r"(r3) : "r"(addr))

#define MMA16816(d, a0, a1, a2, a3, b0, b1) \
    asm volatile("mma.sync.aligned.m16n8k16.row.col.f32.bf16.bf16.f32 " \
        "{%0,%1,%2,%3}, {%4,%5,%6,%7}, {%8,%9}, {%0,%1,%2,%3};" \
        : "+f"((d)[0]), "+f"((d)[1]), "+f"((d)[2]), "+f"((d)[3]) \
        : "r"(a0), "r"(a1), "r"(a2), "r"(a3), "r"(b0), "r"(b1))

__device__ __forceinline__ uint32_t pack2(__nv_bfloat16 a, __nv_bfloat16 b) {
    return (uint32_t)__bfloat16_as_ushort(a) | ((uint32_t)__bfloat16_as_ushort(b) << 16);
}
__device__ __forceinline__ float bflo(uint32_t u) {
    return __bfloat162float(__ushort_as_bfloat16((unsigned short)(u & 0xFFFF)));
}
__device__ __forceinline__ float bfhi(uint32_t u) {
    return __bfloat162float(__ushort_as_bfloat16((unsigned short)(u >> 16)));
}

// ---------------------------------------------------------------------------
// K0a: small precomputed operands (DFT matrices, dense kernel splits)
// ---------------------------------------------------------------------------
__global__ void k0_small(const float* __restrict__ dk)
{
    int t = threadIdx.x + blockIdx.x * blockDim.x;
    int stride = blockDim.x * gridDim.x;
    // F2[m=ky*2+p][w]
    for (int i = t; i < 32 * 128; i += stride) {
        int m = i >> 7, w = i & 127;
        int ky = m >> 1, p = m & 1;
        float s, c;
        sincospif((float)(ky * w) * (1.0f / 64.0f), &s, &c);
        g_F2[i] = __float2bfloat16_rn(p == 0 ? c : -s);
    }
    // G2[m=kxi*2+p][k=h*2+q]
    for (int i = t; i < 64 * 256; i += stride) {
        int m = i >> 8, k = i & 255;
        int kxi = m >> 1, p = m & 1;
        int h = k >> 1, q = k & 1;
        int kx = (kxi < 16) ? kxi : (96 + kxi);
        float s, c;
        sincospif((float)(kx * h) * (1.0f / 64.0f), &s, &c);
        float v = (p == 0) ? (q == 0 ? c : s) : (q == 0 ? -s : c);
        g_G2[i] = __float2bfloat16_rn(v);
    }
    // Hinv[(h,p)][(kxi,q)] = inverse-H twiddle / 128
    for (int i = t; i < 256 * 64; i += stride) {
        int m = i >> 6, kq = i & 63;
        int h = m >> 1, p = m & 1;
        int kxi = kq >> 1, q = kq & 1;
        int kx = (kxi < 16) ? kxi : (96 + kxi);
        float s, c;
        sincospif((float)(kx * h) * (1.0f / 64.0f), &s, &c);
        float v = (p == 0) ? (q == 0 ? c : -s) : (q == 0 ? s : c);
        g_Hinv[i] = __float2bfloat16_rn(v * (1.0f / 128.0f));
    }
    // T[w][j]
    for (int i = t; i < WW * 32; i += stride) {
        int w = i >> 5, j = i & 31, ky = j & 15;
        float s, c;
        sincospif((float)(ky * w) * (1.0f / 64.0f), &s, &c);
        float sc = (ky == 0) ? (1.0f / 128.0f) : (2.0f / 128.0f);
        g_T[i] = __float2bfloat16_rn((j < 16) ? c * sc : -s * sc);
    }
    // Bk[c][k]: K_hi | K_lo
    for (int i = t; i < CC * 128; i += stride) {
        int c = i >> 7, k = i & 127;
        int kk = k & 63;
        float v = dk[kk * 64 + c];
        __nv_bfloat16 hi = __float2bfloat16_rn(v);
        g_Bk[i] = (k < 64) ? hi : __float2bfloat16_rn(v - __bfloat162float(hi));
    }
}

// ---------------------------------------------------------------------------
// K0b: pack complex mode-mixing weights into real 2x2-block bf16 W2
//   W2[kq][(i,q)][(o,p)]: q=0: (p0: Wr, p1: Wi);  q=1: (p0: -Wi, p1: Wr)
// ---------------------------------------------------------------------------
__global__ void k0_w2(const float* __restrict__ w1r, const float* __restrict__ w1i,
                      const float* __restrict__ w2r, const float* __restrict__ w2i)
{
    int t = threadIdx.x + blockIdx.x * blockDim.x;
    int stride = blockDim.x * gridDim.x;
    uint32_t* dst = (uint32_t*)g_W2;
    for (int i = t; i < 512 * 128 * 64; i += stride) {
        int o    = i & 63;
        int iq   = (i >> 6) & 127;
        int ii   = iq >> 1, q = iq & 1;
        int m512 = i >> 13;
        int kxi = m512 >> 4, ky = m512 & 15;
        const float* wr;
        const float* wi;
        if (kxi < 16) { size_t off = (size_t)(kxi * 16 + ky) * 4096; wr = w1r + off; wi = w1i + off; }
        else          { size_t off = (size_t)((kxi - 16) * 16 + ky) * 4096; wr = w2r + off; wi = w2i + off; }
        float vr = __ldg(wr + ii * 64 + o);
        float vi = __ldg(wi + ii * 64 + o);
        float v0 = (q == 0) ? vr : -vi;   // p=0
        float v1 = (q == 0) ? vi :  vr;   // p=1
        dst[i] = pack2(__float2bfloat16_rn(v0), __float2bfloat16_rn(v1));
    }
}

// ---------------------------------------------------------------------------
// K1 (mma): per (b,h): P1[32 m=(ky,p), 64 c] = F2[32x128] @ x[128 w, 64 c]
// ---------------------------------------------------------------------------
#define K1_SA 136
#define K1_SX 72
#define K1_SMEM_A 0
#define K1_SMEM_X (32 * K1_SA * 2)
#define K1_SMEM_TOTAL (K1_SMEM_X + 4 * 128 * K1_SX * 2)

__global__ __launch_bounds__(256) void k1_mma(const float* __restrict__ x)
{
    extern __shared__ char sm[];
    const uint32_t sbase = smem_u32(sm);
    const int b    = blockIdx.x >> 5;
    const int hg   = blockIdx.x & 31;
    const int t    = threadIdx.x;
    const int warp = t >> 5;
    const int lane = t & 31;

    {
        const uint32_t* src = (const uint32_t*)g_F2;
        for (int i = t; i < 32 * 64; i += 256) {
            int m = i >> 6, kp = i & 63;
            *(uint32_t*)(sm + K1_SMEM_A + m * K1_SA * 2 + kp * 4) = src[i];
        }
    }
    {
        const float4* xin = (const float4*)(x + ((size_t)(b * HH + hg * 4)) * WW * CC);
        for (int i = t; i < 4 * 128 * 16; i += 256) {
            float4 v = xin[i];
            int hl = i >> 11, w = (i >> 4) & 127, c4 = i & 15;
            uint32_t u0 = pack2(__float2bfloat16_rn(v.x), __float2bfloat16_rn(v.y));
            uint32_t u1 = pack2(__float2bfloat16_rn(v.z), __float2bfloat16_rn(v.w));
            *(uint2*)(sm + K1_SMEM_X + ((hl * 128 + w) * K1_SX + c4 * 4) * 2) = make_uint2(u0, u1);
        }
    }
    __syncthreads();

    const int hl = warp >> 1, nh = warp & 1;
    const uint32_t Ab = sbase + K1_SMEM_A;
    const uint32_t Xb = sbase + K1_SMEM_X + hl * 128 * K1_SX * 2;

    float acc[2][4][4];
    #pragma unroll
    for (int mt = 0; mt < 2; mt++)
        #pragma unroll
        for (int nt = 0; nt < 4; nt++)
            #pragma unroll
            for (int q = 0; q < 4; q++) acc[mt][nt][q] = 0.f;

    const int arow = lane & 15;
    const int acol = (lane >> 4) * 8;
    const int brow = (lane & 7) + ((lane >> 3) & 1) * 8;
    const int bcol = (lane >> 4) * 8;

    #pragma unroll
    for (int ks = 0; ks < 8; ks++) {
        uint32_t a[2][4];
        #pragma unroll
        for (int mt = 0; mt < 2; mt++) {
            uint32_t addr = Ab + (uint32_t)((mt * 16 + arow) * K1_SA + ks * 16 + acol) * 2;
            LDSM4(a[mt][0], a[mt][1], a[mt][2], a[mt][3], addr);
        }
        #pragma unroll
        for (int np = 0; np < 2; np++) {
            uint32_t b0, b1, b2, b3;
            uint32_t addr = Xb + (uint32_t)((ks * 16 + brow) * K1_SX + nh * 32 + np * 16 + bcol) * 2;
            LDSM4T(b0, b1, b2, b3, addr);
            #pragma unroll
            for (int mt = 0; mt < 2; mt++) {
                MMA16816(acc[mt][np * 2],     a[mt][0], a[mt][1], a[mt][2], a[mt][3], b0, b1);
                MMA16816(acc[mt][np * 2 + 1], a[mt][0], a[mt][1], a[mt][2], a[mt][3], b2, b3);
            }
        }
    }

    const int h = hg * 4 + hl;
    #pragma unroll
    for (int mt = 0; mt < 2; mt++)
        #pragma unroll
        for (int nt = 0; nt < 4; nt++)
            #pragma unroll
            for (int half = 0; half < 2; half++) {
                int m = mt * 16 + (lane >> 2) + half * 8;
                int ky = m >> 1, p = m & 1;
                int c = nh * 32 + nt * 8 + 2 * (lane & 3);
                uint32_t v = pack2(__float2bfloat16_rn(acc[mt][nt][half * 2]),
                                   __float2bfloat16_rn(acc[mt][nt][half * 2 + 1]));
                *(uint32_t*)&g_P1b[(((size_t)b * 16 + ky) * 256 + h * 2 + p) * 64 + c] = v;
            }
}

// ---------------------------------------------------------------------------
// K2 (mma): per (b,ky): X[64 m=(kxi,p), 64 c] = G2[64x256] @ P1b[256,64]
// Output bf16 into g_X2[kxi][ky][b][(c,q=p)]
// ---------------------------------------------------------------------------
#define K2_SA 264
#define K2_SMEM_A 0
#define K2_SMEM_B (64 * K2_SA * 2)
#define K2_SMEM_TOTAL (K2_SMEM_B + 256 * K1_SX * 2)

__global__ __launch_bounds__(256) void k2_mma()
{
    extern __shared__ char sm[];
    const uint32_t sbase = smem_u32(sm);
    const int b    = blockIdx.x >> 4;
    const int ky   = blockIdx.x & 15;
    const int t    = threadIdx.x;
    const int warp = t >> 5;
    const int lane = t & 31;

    {
        const uint32_t* ga = (const uint32_t*)g_G2;
        for (int i = t; i < 64 * 128; i += 256) {
            int m = i >> 7, kp = i & 127;
            *(uint32_t*)(sm + K2_SMEM_A + (m * K2_SA + kp * 2) * 2) = ga[i];
        }
        const uint32_t* gb = (const uint32_t*)(g_P1b + ((size_t)(b * 16 + ky)) * 256 * 64);
        for (int i = t; i < 256 * 32; i += 256) {
            int r = i >> 5, cp = i & 31;
            *(uint32_t*)(sm + K2_SMEM_B + (r * K1_SX + cp * 2) * 2) = gb[i];
        }
    }
    __syncthreads();

    const int mi = warp >> 1, nh = warp & 1;
    float acc[4][4];
    #pragma unroll
    for (int nt = 0; nt < 4; nt++)
        #pragma unroll
        for (int q = 0; q < 4; q++) acc[nt][q] = 0.f;

    const int arow = lane & 15;
    const int acol = (lane >> 4) * 8;
    const int brow = (lane & 7) + ((lane >> 3) & 1) * 8;
    const int bcol = (lane >> 4) * 8;

    #pragma unroll
    for (int ks = 0; ks < 16; ks++) {
        uint32_t a0, a1, a2, a3;
        uint32_t aaddr = sbase + K2_SMEM_A + (uint32_t)((mi * 16 + arow) * K2_SA + ks * 16 + acol) * 2;
        LDSM4(a0, a1, a2, a3, aaddr);
        #pragma unroll
        for (int np = 0; np < 2; np++) {
            uint32_t b0, b1, b2, b3;
            uint32_t baddr = sbase + K2_SMEM_B
                + (uint32_t)((ks * 16 + brow) * K1_SX + nh * 32 + np * 16 + bcol) * 2;
            LDSM4T(b0, b1, b2, b3, baddr);
            MMA16816(acc[np * 2],     a0, a1, a2, a3, b0, b1);
            MMA16816(acc[np * 2 + 1], a0, a1, a2, a3, b2, b3);
        }
    }

    #pragma unroll
    for (int nt = 0; nt < 4; nt++)
        #pragma unroll
        for (int half = 0; half < 2; half++) {
            int m = mi * 16 + (lane >> 2) + half * 8;
            int kxi = m >> 1, p = m & 1;
            int c = nh * 32 + nt * 8 + 2 * (lane & 3);
            size_t base = ((size_t)(kxi * 16 + ky) * 32 + b) * 128;
            g_X2[base + (size_t)c * 2 + p]       = __float2bfloat16_rn(acc[nt][half * 2]);
            g_X2[base + (size_t)(c + 1) * 2 + p] = __float2bfloat16_rn(acc[nt][half * 2 + 1]);
        }
}

// ---------------------------------------------------------------------------
// K3 (mma): per (kxi,ky): Y[32 b, 128 (o,p)] = X2[32 x 128] @ W2[128 x 128]
// ---------------------------------------------------------------------------
__global__ __launch_bounds__(256) void k3_mma()
{
    __shared__ __nv_bfloat16 sA[32 * 136];
    __shared__ __nv_bfloat16 sB[128 * 136];
    const int kq   = blockIdx.x;             // kxi*16+ky
    const int kxi  = kq >> 4, ky = kq & 15;
    const int t    = threadIdx.x;
    const int warp = t >> 5;
    const int lane = t & 31;

    {
        const uint32_t* ax = (const uint32_t*)(g_X2 + (size_t)kq * 32 * 128);
        for (int i = t; i < 32 * 64; i += 256) {
            int r = i >> 6, c32 = i & 63;
            *(uint32_t*)(sA + r * 136 + c32 * 2) = ax[i];
        }
        const uint32_t* bw = (const uint32_t*)(g_W2 + (size_t)kq * 128 * 128);
        for (int i = t; i < 128 * 64; i += 256) {
            int r = i >> 6, c32 = i & 63;
            *(uint32_t*)(sB + r * 136 + c32 * 2) = bw[i];
        }
    }
    __syncthreads();

    const uint32_t sAb = smem_u32(sA);
    const uint32_t sBb = smem_u32(sB);
    float acc[2][2][4];
    #pragma unroll
    for (int mt = 0; mt < 2; mt++)
        #pragma unroll
        for (int g = 0; g < 2; g++)
            #pragma unroll
            for (int q = 0; q < 4; q++) acc[mt][g][q] = 0.f;

    const int arow = lane & 15;
    const int acol = (lane >> 4) * 8;
    const int bkr  = (lane & 7) + ((lane >> 3) & 1) * 8;
    const int bcol = (lane >> 4) * 8;

    #pragma unroll
    for (int ks = 0; ks < 8; ks++) {
        uint32_t a[2][4];
        #pragma unroll
        for (int mt = 0; mt < 2; mt++)
            LDSM4(a[mt][0], a[mt][1], a[mt][2], a[mt][3],
                  sAb + (uint32_t)((mt * 16 + arow) * 136 + ks * 16 + acol) * 2);
        uint32_t b0, b1, b2, b3;
        LDSM4T(b0, b1, b2, b3,
               sBb + (uint32_t)((ks * 16 + bkr) * 136 + warp * 16 + bcol) * 2);
        #pragma unroll
        for (int mt = 0; mt < 2; mt++) {
            MMA16816(acc[mt][0], a[mt][0], a[mt][1], a[mt][2], a[mt][3], b0, b1);
            MMA16816(acc[mt][1], a[mt][0], a[mt][1], a[mt][2], a[mt][3], b2, b3);
        }
    }

    #pragma unroll
    for (int mt = 0; mt < 2; mt++)
        #pragma unroll
        for (int g = 0; g < 2; g++)
            #pragma unroll
            for (int half = 0; half < 2; half++) {
                int bi = mt * 16 + (lane >> 2) + half * 8;
                int n  = warp * 16 + g * 8 + 2 * (lane & 3);
                int o  = n >> 1;                     // n even: p=0 then p=1
                size_t yb = (((size_t)bi * 16 + ky) * 64 + kxi * 2);
                g_Y2[yb * 64 + o]        = __float2bfloat16_rn(acc[mt][g][half * 2]);
                g_Y2[(yb + 1) * 64 + o]  = __float2bfloat16_rn(acc[mt][g][half * 2 + 1]);
            }
}

// ---------------------------------------------------------------------------
// K4 (mma): per (b,ky): Z[256 (h,p), 64 c] = Hinv[256x64] @ Y2[64x64]
// Writes bf16 g_Z2[bh][c][p*16+ky]
// ---------------------------------------------------------------------------
__global__ __launch_bounds__(256) void k4_mma()
{
    __shared__ __nv_bfloat16 sA[256 * 72];
    __shared__ __nv_bfloat16 sB[64 * 72];
    const int b    = blockIdx.x >> 4;
    const int ky   = blockIdx.x & 15;
    const int t    = threadIdx.x;
    const int warp = t >> 5;
    const int lane = t & 31;

    {
        const uint32_t* ah = (const uint32_t*)g_Hinv;
        for (int i = t; i < 256 * 32; i += 256) {
            int r = i >> 5, c32 = i & 31;
            *(uint32_t*)(sA + r * 72 + c32 * 2) = ah[i];
        }
        const uint32_t* by = (const uint32_t*)(g_Y2 + ((size_t)b * 16 + ky) * 64 * 64);
        for (int i = t; i < 64 * 32; i += 256) {
            int r = i >> 5, c32 = i & 31;
            *(uint32_t*)(sB + r * 72 + c32 * 2) = by[i];
        }
    }
    __syncthreads();

    const uint32_t sAb = smem_u32(sA);
    const uint32_t sBb = smem_u32(sB);
    const int wm = warp >> 1, wn = warp & 1;

    float acc[4][4][4];
    #pragma unroll
    for (int mt = 0; mt < 4; mt++)
        #pragma unroll
        for (int g = 0; g < 4; g++)
            #pragma unroll
            for (int q = 0; q < 4; q++) acc[mt][g][q] = 0.f;

    const int arow = lane & 15;
    const int acol = (lane >> 4) * 8;
    const int bkr  = (lane & 7) + ((lane >> 3) & 1) * 8;
    const int bcol = (lane >> 4) * 8;

    #pragma unroll
    for (int ks = 0; ks < 4; ks++) {
        uint32_t a[4][4];
        #pragma unroll
        for (int mt = 0; mt < 4; mt++)
            LDSM4(a[mt][0], a[mt][1], a[mt][2], a[mt][3],
                  sAb + (uint32_t)((wm * 64 + mt * 16 + arow) * 72 + ks * 16 + acol) * 2);
        #pragma unroll
        for (int np = 0; np < 2; np++) {
            uint32_t b0, b1, b2, b3;
            LDSM4T(b0, b1, b2, b3,
                   sBb + (uint32_t)((ks * 16 + bkr) * 72 + wn * 32 + np * 16 + bcol) * 2);
            #pragma unroll
            for (int mt = 0; mt < 4; mt++) {
                MMA16816(acc[mt][np * 2],     a[mt][0], a[mt][1], a[mt][2], a[mt][3], b0, b1);
                MMA16816(acc[mt][np * 2 + 1], a[mt][0], a[mt][1], a[mt][2], a[mt][3], b2, b3);
            }
        }
    }

    #pragma unroll
    for (int mt = 0; mt < 4; mt++)
        #pragma unroll
        for (int g = 0; g < 4; g++)
            #pragma unroll
            for (int half = 0; half < 2; half++) {
                int m = wm * 64 + mt * 16 + (lane >> 2) + half * 8;
                int h = m >> 1, p = m & 1;
                int n = wn * 32 + g * 8 + 2 * (lane & 3);
                size_t base = (((size_t)b * 128 + h) * 64 + n) * 32 + p * 16 + ky;
                g_Z2[base]      = __float2bfloat16_rn(acc[mt][g][half * 2]);
                g_Z2[base + 32] = __float2bfloat16_rn(acc[mt][g][half * 2 + 1]);
            }
}

// ---------------------------------------------------------------------------
// K5: mma.sync bf16 GEMM per (b,h)
// ---------------------------------------------------------------------------
#define SA 168
#define K5_BIAS 0
#define K5_A    256
#define K5_B    (256 + 128 * SA * 2)
#define K5_SMEM (K5_B + 64 * SA * 2)

__global__ __launch_bounds__(256) void k5_mma(const float* __restrict__ x,
                                              const float* __restrict__ bias,
                                              float* __restrict__ out)
{
    extern __shared__ char smem[];
    const uint32_t sbase = smem_u32(smem);
    const int bh   = blockIdx.x;
    const int t    = threadIdx.x;
    const int warp = t >> 5;
    const int lane = t & 31;

    {
        const int w  = t >> 1;
        const int c0 = (t & 1) * 32;
        const float4* xr4 = (const float4*)(x + (size_t)bh * 8192 + (size_t)w * 64 + c0);
        #pragma unroll
        for (int ch = 0; ch < 4; ch++) {
            uint32_t uh[2], ul[2];
            #pragma unroll
            for (int q = 0; q < 2; q++) {
                float4 v = xr4[ch * 2 + q];
                __nv_bfloat16 h0 = __float2bfloat16_rn(v.x), h1 = __float2bfloat16_rn(v.y);
                __nv_bfloat16 h2 = __float2bfloat16_rn(v.z), h3 = __float2bfloat16_rn(v.w);
                uh[q] = pack2(h0, h1);
                ul[q] = pack2(__float2bfloat16_rn(v.x - __bfloat162float(h0)),
                              __float2bfloat16_rn(v.y - __bfloat162float(h1)));
                uint32_t uh2 = pack2(h2, h3);
                uint32_t ul2 = pack2(__float2bfloat16_rn(v.z - __bfloat162float(h2)),
                                     __float2bfloat16_rn(v.w - __bfloat162float(h3)));
                if (q == 0) { *(uint2*)(smem + K5_A + (w * SA + c0 + ch * 8) * 2)      = make_uint2(uh[0], uh2);
                              *(uint2*)(smem + K5_A + (w * SA + 64 + c0 + ch * 8) * 2) = make_uint2(ul[0], ul2); }
                else        { *(uint2*)(smem + K5_A + (w * SA + c0 + ch * 8 + 4) * 2)      = make_uint2(uh[1], uh2);
                              *(uint2*)(smem + K5_A + (w * SA + 64 + c0 + ch * 8 + 4) * 2) = make_uint2(ul[1], ul2); }
            }
        }
    }
    if (t < 128) {
        const int w = t;
        const uint4* ts = (const uint4*)(g_T + w * 32);
        #pragma unroll
        for (int ch = 0; ch < 4; ch++)
            *(uint4*)(smem + K5_A + (w * SA + 128 + ch * 8) * 2) = ts[ch];
    }
    {
        const int c = t >> 2;
        const int q = t & 3;
        if (q < 2) {
            const uint4* src = (const uint4*)(g_Bk + c * 128 + q * 64);
            #pragma unroll
            for (int ch = 0; ch < 8; ch++)
                *(uint4*)(smem + K5_B + (c * SA + q * 64 + ch * 8) * 2) = src[ch];
        } else {
            const uint4* zsrc = (const uint4*)(g_Z2 + ((size_t)bh * 64 + c) * 32);
            int j0 = (q - 2) * 16;
            *(uint4*)(smem + K5_B + (c * SA + 128 + j0) * 2)     = zsrc[(q - 2) * 2];
            *(uint4*)(smem + K5_B + (c * SA + 128 + j0 + 8) * 2) = zsrc[(q - 2) * 2 + 1];
        }
    }
    if (t < 64) ((float*)(smem + K5_BIAS))[t] = bias[t];

    __syncthreads();

    float acc[8][4];
    #pragma unroll
    for (int nt = 0; nt < 8; nt++) {
        acc[nt][0] = 0.f; acc[nt][1] = 0.f; acc[nt][2] = 0.f; acc[nt][3] = 0.f;
    }

    const int arow  = warp * 16 + (lane & 7) + ((lane >> 3) & 1) * 8;
    const int akoff = (lane >> 4) * 8;
    const int brow  = (lane & 7) + (lane >> 4) * 8;
    const int bkoff = ((lane >> 3) & 1) * 8;

    const int passes[4][3] = { {0, 0, 4}, {0, 64, 4}, {64, 0, 4}, {128, 128, 2} };
    #pragma unroll
    for (int p = 0; p < 4; p++) {
        const int kA = passes[p][0], kB = passes[p][1], nks = passes[p][2];
        #pragma unroll
        for (int ks = 0; ks < 4; ks++) {
            if (ks >= nks) break;
            uint32_t a0, a1, a2, a3;
            uint32_t aaddr = sbase + K5_A + (uint32_t)(arow * SA + kA + ks * 16 + akoff) * 2;
            LDSM4(a0, a1, a2, a3, aaddr);
            #pragma unroll
            for (int nt2 = 0; nt2 < 4; nt2++) {
                uint32_t b0, b1, b2, b3;
                uint32_t baddr = sbase + K5_B
                    + (uint32_t)((nt2 * 16 + brow) * SA + kB + ks * 16 + bkoff) * 2;
                LDSM4(b0, b1, b2, b3, baddr);
                MMA16816(acc[2 * nt2],     a0, a1, a2, a3, b0, b1);
                MMA16816(acc[2 * nt2 + 1], a0, a1, a2, a3, b2, b3);
            }
        }
    }

    const int r0 = warp * 16 + (lane >> 2);
    const float* bs = (const float*)(smem + K5_BIAS);
    #pragma unroll
    for (int half = 0; half < 2; half++) {
        const int r = r0 + half * 8;
        float* orow = out + (size_t)bh * 8192 + (size_t)r * 64;
        #pragma unroll
        for (int nt = 0; nt < 8; nt++) {
            const int c = nt * 8 + 2 * (lane & 3);
            uint32_t hp = *(const uint32_t*)(smem + K5_A + (r * SA + c) * 2);
            uint32_t lp = *(const uint32_t*)(smem + K5_A + (r * SA + 64 + c) * 2);
            float res0 = bflo(hp) + bflo(lp);
            float res1 = bfhi(hp) + bfhi(lp);
            float s0 = acc[nt][half * 2 + 0] + res0 + bs[c];
            float s1 = acc[nt][half * 2 + 1] + res1 + bs[c + 1];
            float u0 = 0.7978845608028654f * (s0 + 0.044715f * s0 * s0 * s0);
            float u1 = 0.7978845608028654f * (s1 + 0.044715f * s1 * s1 * s1);
            float g0 = s0 * __frcp_rn(1.0f + __expf(-2.0f * u0));
            float g1 = s1 * __frcp_rn(1.0f + __expf(-2.0f * u1));
            *(float2*)(orow + c) = make_float2(g0, g1);
        }
    }
}

// ---------------------------------------------------------------------------
// Launch
// ---------------------------------------------------------------------------
extern "C" void kernel_launch(void* const* d_in, const int* in_sizes, int n_in,
                              void* d_out, int out_size)
{
    const float* x   = (const float*)d_in[0];
    const float* w1r = (const float*)d_in[1];
    const float* w1i = (const float*)d_in[2];
    const float* w2r = (const float*)d_in[3];
    const float* w2i = (const float*)d_in[4];
    const float* dk  = (const float*)d_in[5];
    const float* db  = (const float*)d_in[6];
    float* out = (float*)d_out;

    static int configured = 0;
    if (!configured) {
        cudaFuncSetAttribute(k1_mma, cudaFuncAttributeMaxDynamicSharedMemorySize, K1_SMEM_TOTAL);
        cudaFuncSetAttribute(k2_mma, cudaFuncAttributeMaxDynamicSharedMemorySize, K2_SMEM_TOTAL);
        cudaFuncSetAttribute(k5_mma, cudaFuncAttributeMaxDynamicSharedMemorySize, K5_SMEM);
        configured = 1;
    }

    k0_small<<<48, 256>>>(dk);
    k0_w2  <<<256, 256>>>(w1r, w1i, w2r, w2i);
    k1_mma <<<BB * 32, 256, K1_SMEM_TOTAL>>>(x);
    k2_mma <<<BB * MY, 256, K2_SMEM_TOTAL>>>();
    k3_mma <<<512, 256>>>();
    k4_mma <<<BB * MY, 256>>>();
    k5_mma <<<BB * HH, 256, K5_SMEM>>>(x, db, out);
}

// round 7
// speedup vs baseline: 1.4496x; 1.4496x over previous
#include <cuda_runtime.h>
#include <cuda_bf16.h>
#include <math.h>
#include <cstdint>

// Problem constants
#define BB 32
#define HH 128
#define WW 128
#define CC 64
#define MY 16
#define NKX 32   // 16 positive kx + 16 negative kx (112..127)

// ---------------------------------------------------------------------------
// Scratch (static device globals — no allocations allowed)
// ---------------------------------------------------------------------------
__device__ __align__(16) __nv_bfloat16 g_P1b[BB * MY * 256 * CC];   // [b][ky][h*2+p][c]
__device__ __align__(16) __nv_bfloat16 g_X2 [NKX * MY * BB * 128];  // [kxi][ky][b][(c,q)]
__device__ __align__(16) __nv_bfloat16 g_Y2 [BB * MY * 64 * CC];    // [b][ky][(kxi,q)][c]
__device__ __align__(16) __nv_bfloat16 g_Z2 [BB * 32 * HH * CC];    // [b][p*16+ky][h][c]
__device__ __align__(16) __nv_bfloat16 g_Hinv[256 * 64];            // [(h,p)][(kxi,q)]
__device__ __align__(16) __nv_bfloat16 g_F2 [32 * 128];             // [ky*2+p][w]
__device__ __align__(16) __nv_bfloat16 g_G2 [64 * 256];             // [kxi*2+p][h*2+q]
__device__ __align__(16) __nv_bfloat16 g_T  [WW * 32];              // [w][j] inverse-W DFT
__device__ __align__(16) __nv_bfloat16 g_Bk [CC * 128];             // [c][k]: K_hi|K_lo

// ---------------------------------------------------------------------------
// mma.sync helpers
// ---------------------------------------------------------------------------
__device__ __forceinline__ uint32_t smem_u32(const void* p) {
    uint32_t a;
    asm("{ .reg .u64 t; cvta.to.shared.u64 t, %1; cvt.u32.u64 %0, t; }" : "=r"(a) : "l"(p));
    return a;
}
#define LDSM4(r0, r1, r2, r3, addr) \
    asm volatile("ldmatrix.sync.aligned.m8n8.x4.shared.b16 {%0,%1,%2,%3}, [%4];" \
        : "=r"(r0), "=r"(r1), "=r"(r2), "=r"(r3) : "r"(addr))
#define LDSM4T(r0, r1, r2, r3, addr) \
    asm volatile("ldmatrix.sync.aligned.m8n8.x4.trans.shared.b16 {%0,%1,%2,%3}, [%4];" \
        : "=r"(r0), "=r"(r1), "=r"(r2), "=r"(r3) : "r"(addr))

#define MMA16816(d, a0, a1, a2, a3, b0, b1) \
    asm volatile("mma.sync.aligned.m16n8k16.row.col.f32.bf16.bf16.f32 " \
        "{%0,%1,%2,%3}, {%4,%5,%6,%7}, {%8,%9}, {%0,%1,%2,%3};" \
        : "+f"((d)[0]), "+f"((d)[1]), "+f"((d)[2]), "+f"((d)[3]) \
        : "r"(a0), "r"(a1), "r"(a2), "r"(a3), "r"(b0), "r"(b1))

__device__ __forceinline__ uint32_t pack2(__nv_bfloat16 a, __nv_bfloat16 b) {
    return (uint32_t)__bfloat16_as_ushort(a) | ((uint32_t)__bfloat16_as_ushort(b) << 16);
}
__device__ __forceinline__ uint32_t pack2f(float a, float b) {
    return pack2(__float2bfloat16_rn(a), __float2bfloat16_rn(b));
}
__device__ __forceinline__ float bflo(uint32_t u) {
    return __bfloat162float(__ushort_as_bfloat16((unsigned short)(u & 0xFFFF)));
}
__device__ __forceinline__ float bfhi(uint32_t u) {
    return __bfloat162float(__ushort_as_bfloat16((unsigned short)(u >> 16)));
}

// ---------------------------------------------------------------------------
// K0: small precomputed operands
// ---------------------------------------------------------------------------
__global__ void k0_small(const float* __restrict__ dk)
{
    int t = threadIdx.x + blockIdx.x * blockDim.x;
    int stride = blockDim.x * gridDim.x;
    for (int i = t; i < 32 * 128; i += stride) {
        int m = i >> 7, w = i & 127;
        int ky = m >> 1, p = m & 1;
        float s, c;
        sincospif((float)(ky * w) * (1.0f / 64.0f), &s, &c);
        g_F2[i] = __float2bfloat16_rn(p == 0 ? c : -s);
    }
    for (int i = t; i < 64 * 256; i += stride) {
        int m = i >> 8, k = i & 255;
        int kxi = m >> 1, p = m & 1;
        int h = k >> 1, q = k & 1;
        int kx = (kxi < 16) ? kxi : (96 + kxi);
        float s, c;
        sincospif((float)(kx * h) * (1.0f / 64.0f), &s, &c);
        float v = (p == 0) ? (q == 0 ? c : s) : (q == 0 ? -s : c);
        g_G2[i] = __float2bfloat16_rn(v);
    }
    for (int i = t; i < 256 * 64; i += stride) {
        int m = i >> 6, kq = i & 63;
        int h = m >> 1, p = m & 1;
        int kxi = kq >> 1, q = kq & 1;
        int kx = (kxi < 16) ? kxi : (96 + kxi);
        float s, c;
        sincospif((float)(kx * h) * (1.0f / 64.0f), &s, &c);
        float v = (p == 0) ? (q == 0 ? c : -s) : (q == 0 ? s : c);
        g_Hinv[i] = __float2bfloat16_rn(v * (1.0f / 128.0f));
    }
    for (int i = t; i < WW * 32; i += stride) {
        int w = i >> 5, j = i & 31, ky = j & 15;
        float s, c;
        sincospif((float)(ky * w) * (1.0f / 64.0f), &s, &c);
        float sc = (ky == 0) ? (1.0f / 128.0f) : (2.0f / 128.0f);
        g_T[i] = __float2bfloat16_rn((j < 16) ? c * sc : -s * sc);
    }
    for (int i = t; i < CC * 128; i += stride) {
        int c = i >> 7, k = i & 127;
        int kk = k & 63;
        float v = dk[kk * 64 + c];
        __nv_bfloat16 hi = __float2bfloat16_rn(v);
        g_Bk[i] = (k < 64) ? hi : __float2bfloat16_rn(v - __bfloat162float(hi));
    }
}

// ---------------------------------------------------------------------------
// K1 (mma): per (b, 4h): P1[32 m=(ky,p), 64 c] = F2[32x128] @ x[128 w, 64 c]
// Coalesced epilogue via smem staging.
// ---------------------------------------------------------------------------
#define K1_SA 136
#define K1_SX 72
#define K1_SMEM_A 0
#define K1_SMEM_X (32 * K1_SA * 2)
#define K1_SMEM_TOTAL (K1_SMEM_X + 4 * 128 * K1_SX * 2)

__global__ __launch_bounds__(256) void k1_mma(const float* __restrict__ x)
{
    extern __shared__ char sm[];
    const uint32_t sbase = smem_u32(sm);
    const int b    = blockIdx.x >> 5;
    const int hg   = blockIdx.x & 31;
    const int t    = threadIdx.x;
    const int warp = t >> 5;
    const int lane = t & 31;

    {
        const uint32_t* src = (const uint32_t*)g_F2;
        for (int i = t; i < 32 * 64; i += 256) {
            int m = i >> 6, kp = i & 63;
            *(uint32_t*)(sm + K1_SMEM_A + m * K1_SA * 2 + kp * 4) = src[i];
        }
    }
    {
        const float4* xin = (const float4*)(x + ((size_t)(b * HH + hg * 4)) * WW * CC);
        for (int i = t; i < 4 * 128 * 16; i += 256) {
            float4 v = xin[i];
            int hl = i >> 11, w = (i >> 4) & 127, c4 = i & 15;
            uint32_t u0 = pack2f(v.x, v.y);
            uint32_t u1 = pack2f(v.z, v.w);
            *(uint2*)(sm + K1_SMEM_X + ((hl * 128 + w) * K1_SX + c4 * 4) * 2) = make_uint2(u0, u1);
        }
    }
    __syncthreads();

    const int hl = warp >> 1, nh = warp & 1;
    const uint32_t Ab = sbase + K1_SMEM_A;
    const uint32_t Xb = sbase + K1_SMEM_X + hl * 128 * K1_SX * 2;

    float acc[2][4][4];
    #pragma unroll
    for (int mt = 0; mt < 2; mt++)
        #pragma unroll
        for (int nt = 0; nt < 4; nt++)
            #pragma unroll
            for (int q = 0; q < 4; q++) acc[mt][nt][q] = 0.f;

    const int arow = lane & 15;
    const int acol = (lane >> 4) * 8;
    const int brow = (lane & 7) + ((lane >> 3) & 1) * 8;
    const int bcol = (lane >> 4) * 8;

    #pragma unroll
    for (int ks = 0; ks < 8; ks++) {
        uint32_t a[2][4];
        #pragma unroll
        for (int mt = 0; mt < 2; mt++) {
            uint32_t addr = Ab + (uint32_t)((mt * 16 + arow) * K1_SA + ks * 16 + acol) * 2;
            LDSM4(a[mt][0], a[mt][1], a[mt][2], a[mt][3], addr);
        }
        #pragma unroll
        for (int np = 0; np < 2; np++) {
            uint32_t b0, b1, b2, b3;
            uint32_t addr = Xb + (uint32_t)((ks * 16 + brow) * K1_SX + nh * 32 + np * 16 + bcol) * 2;
            LDSM4T(b0, b1, b2, b3, addr);
            #pragma unroll
            for (int mt = 0; mt < 2; mt++) {
                MMA16816(acc[mt][np * 2],     a[mt][0], a[mt][1], a[mt][2], a[mt][3], b0, b1);
                MMA16816(acc[mt][np * 2 + 1], a[mt][0], a[mt][1], a[mt][2], a[mt][3], b2, b3);
            }
        }
    }

    // stage accumulators to smem [128 rows = (ky,hl,p)][72], then coalesced write
    __syncthreads();
    __nv_bfloat16* stg = (__nv_bfloat16*)(sm + K1_SMEM_X);
    #pragma unroll
    for (int mt = 0; mt < 2; mt++)
        #pragma unroll
        for (int nt = 0; nt < 4; nt++)
            #pragma unroll
            for (int half = 0; half < 2; half++) {
                int m = mt * 16 + (lane >> 2) + half * 8;
                int ky = m >> 1, p = m & 1;
                int c = nh * 32 + nt * 8 + 2 * (lane & 3);
                int sr = ky * 8 + hl * 2 + p;
                *(uint32_t*)(stg + sr * 72 + c) =
                    pack2f(acc[mt][nt][half * 2], acc[mt][nt][half * 2 + 1]);
            }
    __syncthreads();
    {
        int sr = t >> 1, seg = t & 1;
        int ky = sr >> 3, hl2 = (sr >> 1) & 3, p = sr & 1;
        size_t row = (((size_t)(b * 16 + ky)) * 256 + (hg * 4 + hl2) * 2 + p) * 64 + seg * 32;
        const uint4* src = (const uint4*)(stg + sr * 72 + seg * 32);
        uint4* dst = (uint4*)(g_P1b + row);
        dst[0] = src[0]; dst[1] = src[1]; dst[2] = src[2]; dst[3] = src[3];
    }
}

// ---------------------------------------------------------------------------
// K2 (mma): per (b,ky): X[64 m=(kxi,p), 64 c] = G2[64x256] @ P1b[256,64]
// Coalesced epilogue via smem staging into g_X2[kxi][ky][b][(c,q)]
// ---------------------------------------------------------------------------
#define K2_SA 264
#define K2_SMEM_A 0
#define K2_SMEM_B (64 * K2_SA * 2)
#define K2_SMEM_TOTAL (K2_SMEM_B + 256 * K1_SX * 2)

__global__ __launch_bounds__(256) void k2_mma()
{
    extern __shared__ char sm[];
    const uint32_t sbase = smem_u32(sm);
    const int b    = blockIdx.x >> 4;
    const int ky   = blockIdx.x & 15;
    const int t    = threadIdx.x;
    const int warp = t >> 5;
    const int lane = t & 31;

    {
        const uint32_t* ga = (const uint32_t*)g_G2;
        for (int i = t; i < 64 * 128; i += 256) {
            int m = i >> 7, kp = i & 127;
            *(uint32_t*)(sm + K2_SMEM_A + (m * K2_SA + kp * 2) * 2) = ga[i];
        }
        const uint32_t* gb = (const uint32_t*)(g_P1b + ((size_t)(b * 16 + ky)) * 256 * 64);
        for (int i = t; i < 256 * 32; i += 256) {
            int r = i >> 5, cp = i & 31;
            *(uint32_t*)(sm + K2_SMEM_B + (r * K1_SX + cp * 2) * 2) = gb[i];
        }
    }
    __syncthreads();

    const int mi = warp >> 1, nh = warp & 1;
    float acc[4][4];
    #pragma unroll
    for (int nt = 0; nt < 4; nt++)
        #pragma unroll
        for (int q = 0; q < 4; q++) acc[nt][q] = 0.f;

    const int arow = lane & 15;
    const int acol = (lane >> 4) * 8;
    const int brow = (lane & 7) + ((lane >> 3) & 1) * 8;
    const int bcol = (lane >> 4) * 8;

    #pragma unroll
    for (int ks = 0; ks < 16; ks++) {
        uint32_t a0, a1, a2, a3;
        uint32_t aaddr = sbase + K2_SMEM_A + (uint32_t)((mi * 16 + arow) * K2_SA + ks * 16 + acol) * 2;
        LDSM4(a0, a1, a2, a3, aaddr);
        #pragma unroll
        for (int np = 0; np < 2; np++) {
            uint32_t b0, b1, b2, b3;
            uint32_t baddr = sbase + K2_SMEM_B
                + (uint32_t)((ks * 16 + brow) * K1_SX + nh * 32 + np * 16 + bcol) * 2;
            LDSM4T(b0, b1, b2, b3, baddr);
            MMA16816(acc[np * 2],     a0, a1, a2, a3, b0, b1);
            MMA16816(acc[np * 2 + 1], a0, a1, a2, a3, b2, b3);
        }
    }

    __syncthreads();
    __nv_bfloat16* stg = (__nv_bfloat16*)sm;   // [64 m][72]
    #pragma unroll
    for (int nt = 0; nt < 4; nt++)
        #pragma unroll
        for (int half = 0; half < 2; half++) {
            int m = mi * 16 + (lane >> 2) + half * 8;
            int c = nh * 32 + nt * 8 + 2 * (lane & 3);
            *(uint32_t*)(stg + m * 72 + c) = pack2f(acc[nt][half * 2], acc[nt][half * 2 + 1]);
        }
    __syncthreads();
    {
        int kxi = t >> 3, seg = t & 7;
        uint32_t vals[8];
        #pragma unroll
        for (int u = 0; u < 8; u++) {
            int j0 = seg * 16 + 2 * u;
            __nv_bfloat16 v0 = stg[(2 * kxi + (j0 & 1)) * 72 + (j0 >> 1)];
            __nv_bfloat16 v1 = stg[(2 * kxi + ((j0 + 1) & 1)) * 72 + ((j0 + 1) >> 1)];
            vals[u] = pack2(v0, v1);
        }
        uint4* dst = (uint4*)(g_X2 + ((size_t)(kxi * 16 + ky) * 32 + b) * 128 + seg * 16);
        dst[0] = make_uint4(vals[0], vals[1], vals[2], vals[3]);
        dst[1] = make_uint4(vals[4], vals[5], vals[6], vals[7]);
    }
}

// ---------------------------------------------------------------------------
// K3 (mma): per (kxi,ky): Y[32 b, 128 (o,p)] = X2[32x128] @ W2[128x128]
// W2 built inline from fp32 w1/w2 during smem fill. Coalesced epilogue.
// ---------------------------------------------------------------------------
__global__ __launch_bounds__(256) void k3_mma(const float* __restrict__ w1r,
                                              const float* __restrict__ w1i,
                                              const float* __restrict__ w2r,
                                              const float* __restrict__ w2i)
{
    __shared__ __nv_bfloat16 sA[32 * 136];
    __shared__ __nv_bfloat16 sB[128 * 136];
    const int kq   = blockIdx.x;             // kxi*16+ky
    const int kxi  = kq >> 4, ky = kq & 15;
    const int t    = threadIdx.x;
    const int warp = t >> 5;
    const int lane = t & 31;

    {
        const uint32_t* ax = (const uint32_t*)(g_X2 + (size_t)kq * 32 * 128);
        for (int i = t; i < 32 * 64; i += 256) {
            int r = i >> 6, c32 = i & 63;
            *(uint32_t*)(sA + r * 136 + c32 * 2) = ax[i];
        }
        // inline W2 expansion from fp32
        const float* wr;
        const float* wi;
        if (kxi < 16) { size_t off = (size_t)(kxi * 16 + ky) * 4096; wr = w1r + off; wi = w1i + off; }
        else          { size_t off = (size_t)((kxi - 16) * 16 + ky) * 4096; wr = w2r + off; wi = w2i + off; }
        const int ii = t >> 2;
        const int o0 = (t & 3) * 16;
        #pragma unroll
        for (int u = 0; u < 8; u++) {
            int o = o0 + 2 * u;
            float2 r2 = *(const float2*)(wr + ii * 64 + o);
            float2 i2 = *(const float2*)(wi + ii * 64 + o);
            *(uint2*)(sB + (2 * ii) * 136 + 2 * o) =
                make_uint2(pack2f(r2.x, i2.x), pack2f(r2.y, i2.y));
            *(uint2*)(sB + (2 * ii + 1) * 136 + 2 * o) =
                make_uint2(pack2f(-i2.x, r2.x), pack2f(-i2.y, r2.y));
        }
    }
    __syncthreads();

    const uint32_t sAb = smem_u32(sA);
    const uint32_t sBb = smem_u32(sB);
    float acc[2][2][4];
    #pragma unroll
    for (int mt = 0; mt < 2; mt++)
        #pragma unroll
        for (int g = 0; g < 2; g++)
            #pragma unroll
            for (int q = 0; q < 4; q++) acc[mt][g][q] = 0.f;

    const int arow = lane & 15;
    const int acol = (lane >> 4) * 8;
    const int bkr  = (lane & 7) + ((lane >> 3) & 1) * 8;
    const int bcol = (lane >> 4) * 8;

    #pragma unroll
    for (int ks = 0; ks < 8; ks++) {
        uint32_t a[2][4];
        #pragma unroll
        for (int mt = 0; mt < 2; mt++)
            LDSM4(a[mt][0], a[mt][1], a[mt][2], a[mt][3],
                  sAb + (uint32_t)((mt * 16 + arow) * 136 + ks * 16 + acol) * 2);
        uint32_t b0, b1, b2, b3;
        LDSM4T(b0, b1, b2, b3,
               sBb + (uint32_t)((ks * 16 + bkr) * 136 + warp * 16 + bcol) * 2);
        #pragma unroll
        for (int mt = 0; mt < 2; mt++) {
            MMA16816(acc[mt][0], a[mt][0], a[mt][1], a[mt][2], a[mt][3], b0, b1);
            MMA16816(acc[mt][1], a[mt][0], a[mt][1], a[mt][2], a[mt][3], b2, b3);
        }
    }

    // stage [32 b][128 = p*64+o] then coalesced write (2 rows of 64 per b)
    __syncthreads();
    __nv_bfloat16* stg = sA;   // 32*136 >= 32*136 staging rows
    #pragma unroll
    for (int mt = 0; mt < 2; mt++)
        #pragma unroll
        for (int g = 0; g < 2; g++)
            #pragma unroll
            for (int half = 0; half < 2; half++) {
                int bi = mt * 16 + (lane >> 2) + half * 8;
                int n  = warp * 16 + g * 8 + 2 * (lane & 3);
                int o  = n >> 1;
                stg[bi * 136 + o]      = __float2bfloat16_rn(acc[mt][g][half * 2]);
                stg[bi * 136 + 64 + o] = __float2bfloat16_rn(acc[mt][g][half * 2 + 1]);
            }
    __syncthreads();
    {
        int b2 = t >> 3, seg = t & 7;
        const uint4* src = (const uint4*)(stg + b2 * 136 + seg * 16);
        uint4* dst = (uint4*)(g_Y2 + (((size_t)(b2 * 16 + ky)) * 64 + kxi * 2) * 64 + seg * 16);
        dst[0] = src[0]; dst[1] = src[1];
    }
}

// ---------------------------------------------------------------------------
// K4 (mma): per (b,ky): Z[256 (h,p), 64 c] = Hinv[256x64] @ Y2[64x64]
// Direct coalesced uint32 stores into g_Z2[b][p*16+ky][h][c]
// ---------------------------------------------------------------------------
__global__ __launch_bounds__(256) void k4_mma()
{
    __shared__ __nv_bfloat16 sA[256 * 72];
    __shared__ __nv_bfloat16 sB[64 * 72];
    const int b    = blockIdx.x >> 4;
    const int ky   = blockIdx.x & 15;
    const int t    = threadIdx.x;
    const int warp = t >> 5;
    const int lane = t & 31;

    {
        const uint32_t* ah = (const uint32_t*)g_Hinv;
        for (int i = t; i < 256 * 32; i += 256) {
            int r = i >> 5, c32 = i & 31;
            *(uint32_t*)(sA + r * 72 + c32 * 2) = ah[i];
        }
        const uint32_t* by = (const uint32_t*)(g_Y2 + ((size_t)b * 16 + ky) * 64 * 64);
        for (int i = t; i < 64 * 32; i += 256) {
            int r = i >> 5, c32 = i & 31;
            *(uint32_t*)(sB + r * 72 + c32 * 2) = by[i];
        }
    }
    __syncthreads();

    const uint32_t sAb = smem_u32(sA);
    const uint32_t sBb = smem_u32(sB);
    const int wm = warp >> 1, wn = warp & 1;

    float acc[4][4][4];
    #pragma unroll
    for (int mt = 0; mt < 4; mt++)
        #pragma unroll
        for (int g = 0; g < 4; g++)
            #pragma unroll
            for (int q = 0; q < 4; q++) acc[mt][g][q] = 0.f;

    const int arow = lane & 15;
    const int acol = (lane >> 4) * 8;
    const int bkr  = (lane & 7) + ((lane >> 3) & 1) * 8;
    const int bcol = (lane >> 4) * 8;

    #pragma unroll
    for (int ks = 0; ks < 4; ks++) {
        uint32_t a[4][4];
        #pragma unroll
        for (int mt = 0; mt < 4; mt++)
            LDSM4(a[mt][0], a[mt][1], a[mt][2], a[mt][3],
                  sAb + (uint32_t)((wm * 64 + mt * 16 + arow) * 72 + ks * 16 + acol) * 2);
        #pragma unroll
        for (int np = 0; np < 2; np++) {
            uint32_t b0, b1, b2, b3;
            LDSM4T(b0, b1, b2, b3,
                   sBb + (uint32_t)((ks * 16 + bkr) * 72 + wn * 32 + np * 16 + bcol) * 2);
            #pragma unroll
            for (int mt = 0; mt < 4; mt++) {
                MMA16816(acc[mt][np * 2],     a[mt][0], a[mt][1], a[mt][2], a[mt][3], b0, b1);
                MMA16816(acc[mt][np * 2 + 1], a[mt][0], a[mt][1], a[mt][2], a[mt][3], b2, b3);
            }
        }
    }

    #pragma unroll
    for (int mt = 0; mt < 4; mt++)
        #pragma unroll
        for (int g = 0; g < 4; g++)
            #pragma unroll
            for (int half = 0; half < 2; half++) {
                int m = wm * 64 + mt * 16 + (lane >> 2) + half * 8;
                int h = m >> 1, p = m & 1;
                int n = wn * 32 + g * 8 + 2 * (lane & 3);
                size_t addr = (((size_t)b * 32 + p * 16 + ky) * 128 + h) * 64 + n;
                *(uint32_t*)(g_Z2 + addr) = pack2f(acc[mt][g][half * 2], acc[mt][g][half * 2 + 1]);
            }
}

// ---------------------------------------------------------------------------
// K5: mma.sync bf16 GEMM per (b,h)
//   A[128 x 160] = [ x_hi | x_lo | T ], SA=168
//   B[ 64 x 128] = [ K_hi | K_lo ],      SB=136
//   Zb[32 j][64 c] (j = p*16+ky), SZ=72, used via ldmatrix.trans in pass 4
// ---------------------------------------------------------------------------
#define SA 168
#define SB 136
#define SZ 72
#define K5_BIAS 0
#define K5_A    256
#define K5_B    (K5_A + 128 * SA * 2)     // 256 + 43008 = 43264
#define K5_ZB   (K5_B + 64 * SB * 2)      // 43264 + 17408 = 60672
#define K5_SMEM (K5_ZB + 32 * SZ * 2)     // 60672 + 4608 = 65280

__global__ __launch_bounds__(256) void k5_mma(const float* __restrict__ x,
                                              const float* __restrict__ bias,
                                              float* __restrict__ out)
{
    extern __shared__ char smem[];
    const uint32_t sbase = smem_u32(smem);
    const int bh   = blockIdx.x;
    const int t    = threadIdx.x;
    const int warp = t >> 5;
    const int lane = t & 31;

    // ---- A fill: x_hi (0..63), x_lo (64..127) ----
    {
        const int w  = t >> 1;
        const int c0 = (t & 1) * 32;
        const float4* xr4 = (const float4*)(x + (size_t)bh * 8192 + (size_t)w * 64 + c0);
        #pragma unroll
        for (int ch = 0; ch < 4; ch++) {
            #pragma unroll
            for (int q = 0; q < 2; q++) {
                float4 v = xr4[ch * 2 + q];
                __nv_bfloat16 h0 = __float2bfloat16_rn(v.x), h1 = __float2bfloat16_rn(v.y);
                __nv_bfloat16 h2 = __float2bfloat16_rn(v.z), h3 = __float2bfloat16_rn(v.w);
                uint32_t uhA = pack2(h0, h1), uhB = pack2(h2, h3);
                uint32_t ulA = pack2(__float2bfloat16_rn(v.x - __bfloat162float(h0)),
                                     __float2bfloat16_rn(v.y - __bfloat162float(h1)));
                uint32_t ulB = pack2(__float2bfloat16_rn(v.z - __bfloat162float(h2)),
                                     __float2bfloat16_rn(v.w - __bfloat162float(h3)));
                *(uint2*)(smem + K5_A + (w * SA + c0 + ch * 8 + q * 4) * 2)      = make_uint2(uhA, uhB);
                *(uint2*)(smem + K5_A + (w * SA + 64 + c0 + ch * 8 + q * 4) * 2) = make_uint2(ulA, ulB);
            }
        }
    }
    // ---- A fill: T block (cols 128..159) ----
    if (t < 128) {
        const int w = t;
        const uint4* ts = (const uint4*)(g_T + w * 32);
        #pragma unroll
        for (int ch = 0; ch < 4; ch++)
            *(uint4*)(smem + K5_A + (w * SA + 128 + ch * 8) * 2) = ts[ch];
    }
    // ---- B fill: K_hi | K_lo ----
    {
        const int c = t >> 2;
        const int q4 = t & 3;
        const uint4* src = (const uint4*)(g_Bk + c * 128 + q4 * 32);
        uint4* dst = (uint4*)(smem + K5_B + (c * SB + q4 * 32) * 2);
        dst[0] = src[0]; dst[1] = src[1]; dst[2] = src[2]; dst[3] = src[3];
    }
    // ---- Zb fill: 32 contiguous 128B rows from g_Z2[b][j][h][c] ----
    {
        const int b = bh >> 7, h = bh & 127;
        const int j = t >> 3, seg = t & 7;
        const uint4* src = (const uint4*)(g_Z2 + (((size_t)b * 32 + j) * 128 + h) * 64 + seg * 8);
        *(uint4*)(smem + K5_ZB + (j * SZ + seg * 8) * 2) = src[0];
    }
    if (t < 64) ((float*)(smem + K5_BIAS))[t] = bias[t];

    __syncthreads();

    float acc[8][4];
    #pragma unroll
    for (int nt = 0; nt < 8; nt++) {
        acc[nt][0] = 0.f; acc[nt][1] = 0.f; acc[nt][2] = 0.f; acc[nt][3] = 0.f;
    }

    const int arow  = warp * 16 + (lane & 7) + ((lane >> 3) & 1) * 8;
    const int akoff = (lane >> 4) * 8;
    const int brow  = (lane & 7) + (lane >> 4) * 8;
    const int bkoff = ((lane >> 3) & 1) * 8;
    const int zrow  = (lane & 7) + ((lane >> 3) & 1) * 8;   // trans-load row (k)
    const int zcol  = (lane >> 4) * 8;                      // trans-load col (n)

    // passes 0..2: dense hi/lo products
    const int passes[3][2] = { {0, 0}, {0, 64}, {64, 0} };
    #pragma unroll
    for (int p = 0; p < 3; p++) {
        const int kA = passes[p][0], kB = passes[p][1];
        #pragma unroll
        for (int ks = 0; ks < 4; ks++) {
            uint32_t a0, a1, a2, a3;
            uint32_t aaddr = sbase + K5_A + (uint32_t)(arow * SA + kA + ks * 16 + akoff) * 2;
            LDSM4(a0, a1, a2, a3, aaddr);
            #pragma unroll
            for (int nt2 = 0; nt2 < 4; nt2++) {
                uint32_t b0, b1, b2, b3;
                uint32_t baddr = sbase + K5_B
                    + (uint32_t)((nt2 * 16 + brow) * SB + kB + ks * 16 + bkoff) * 2;
                LDSM4(b0, b1, b2, b3, baddr);
                MMA16816(acc[2 * nt2],     a0, a1, a2, a3, b0, b1);
                MMA16816(acc[2 * nt2 + 1], a0, a1, a2, a3, b2, b3);
            }
        }
    }
    // pass 3: T (A cols 128..159) x Z (Zb via trans loads)
    #pragma unroll
    for (int ks = 0; ks < 2; ks++) {
        uint32_t a0, a1, a2, a3;
        uint32_t aaddr = sbase + K5_A + (uint32_t)(arow * SA + 128 + ks * 16 + akoff) * 2;
        LDSM4(a0, a1, a2, a3, aaddr);
        #pragma unroll
        for (int nt2 = 0; nt2 < 4; nt2++) {
            uint32_t b0, b1, b2, b3;
            uint32_t baddr = sbase + K5_ZB
                + (uint32_t)((ks * 16 + zrow) * SZ + nt2 * 16 + zcol) * 2;
            LDSM4T(b0, b1, b2, b3, baddr);
            MMA16816(acc[2 * nt2],     a0, a1, a2, a3, b0, b1);
            MMA16816(acc[2 * nt2 + 1], a0, a1, a2, a3, b2, b3);
        }
    }

    const int r0 = warp * 16 + (lane >> 2);
    const float* bs = (const float*)(smem + K5_BIAS);
    #pragma unroll
    for (int half = 0; half < 2; half++) {
        const int r = r0 + half * 8;
        float* orow = out + (size_t)bh * 8192 + (size_t)r * 64;
        #pragma unroll
        for (int nt = 0; nt < 8; nt++) {
            const int c = nt * 8 + 2 * (lane & 3);
            uint32_t hp = *(const uint32_t*)(smem + K5_A + (r * SA + c) * 2);
            uint32_t lp = *(const uint32_t*)(smem + K5_A + (r * SA + 64 + c) * 2);
            float res0 = bflo(hp) + bflo(lp);
            float res1 = bfhi(hp) + bfhi(lp);
            float s0 = acc[nt][half * 2 + 0] + res0 + bs[c];
            float s1 = acc[nt][half * 2 + 1] + res1 + bs[c + 1];
            float u0 = 0.7978845608028654f * (s0 + 0.044715f * s0 * s0 * s0);
            float u1 = 0.7978845608028654f * (s1 + 0.044715f * s1 * s1 * s1);
            float g0 = s0 * __frcp_rn(1.0f + __expf(-2.0f * u0));
            float g1 = s1 * __frcp_rn(1.0f + __expf(-2.0f * u1));
            *(float2*)(orow + c) = make_float2(g0, g1);
        }
    }
}

// ---------------------------------------------------------------------------
// Launch
// ---------------------------------------------------------------------------
extern "C" void kernel_launch(void* const* d_in, const int* in_sizes, int n_in,
                              void* d_out, int out_size)
{
    const float* x   = (const float*)d_in[0];
    const float* w1r = (const float*)d_in[1];
    const float* w1i = (const float*)d_in[2];
    const float* w2r = (const float*)d_in[3];
    const float* w2i = (const float*)d_in[4];
    const float* dk  = (const float*)d_in[5];
    const float* db  = (const float*)d_in[6];
    float* out = (float*)d_out;

    static int configured = 0;
    if (!configured) {
        cudaFuncSetAttribute(k1_mma, cudaFuncAttributeMaxDynamicSharedMemorySize, K1_SMEM_TOTAL);
        cudaFuncSetAttribute(k2_mma, cudaFuncAttributeMaxDynamicSharedMemorySize, K2_SMEM_TOTAL);
        cudaFuncSetAttribute(k5_mma, cudaFuncAttributeMaxDynamicSharedMemorySize, K5_SMEM);
        configured = 1;
    }

    k0_small<<<48, 256>>>(dk);
    k1_mma <<<BB * 32, 256, K1_SMEM_TOTAL>>>(x);
    k2_mma <<<BB * MY, 256, K2_SMEM_TOTAL>>>();
    k3_mma <<<512, 256>>>(w1r, w1i, w2r, w2i);
    k4_mma <<<BB * MY, 256>>>();
    k5_mma <<<BB * HH, 256, K5_SMEM>>>(x, db, out);
}

// round 8
// speedup vs baseline: 1.5438x; 1.0650x over previous
#include <cuda_runtime.h>
#include <cuda_bf16.h>
#include <math.h>
#include <cstdint>

// Problem constants
#define BB 32
#define HH 128
#define WW 128
#define CC 64
#define MY 16
#define NKX 32   // 16 positive kx + 16 negative kx (112..127)

// ---------------------------------------------------------------------------
// Scratch (static device globals — no allocations allowed)
// ---------------------------------------------------------------------------
__device__ __align__(16) __nv_bfloat16 g_P1b[BB * MY * 256 * CC];   // [b][ky][h*2+p][c]
__device__ __align__(16) __nv_bfloat16 g_X2 [NKX * MY * BB * 128];  // [kxi][ky][b][(c,q)]
__device__ __align__(16) __nv_bfloat16 g_Y2 [BB * MY * 64 * CC];    // [b][ky][(kxi,q)][c]
__device__ __align__(16) __nv_bfloat16 g_Z2 [BB * 32 * HH * CC];    // [b][p*16+ky][h][c]
__device__ __align__(16) __nv_bfloat16 g_Hinv[256 * 64];            // [(h,p)][(kxi,q)]
__device__ __align__(16) __nv_bfloat16 g_F2 [32 * 128];             // [ky*2+p][w]
__device__ __align__(16) __nv_bfloat16 g_G2 [64 * 256];             // [kxi*2+p][h*2+q]
__device__ __align__(16) __nv_bfloat16 g_T  [WW * 32];              // [w][j] inverse-W DFT
__device__ __align__(16) __nv_bfloat16 g_Bk [CC * 128];             // [c][k]: K_hi|K_lo

// ---------------------------------------------------------------------------
// mma.sync helpers
// ---------------------------------------------------------------------------
__device__ __forceinline__ uint32_t smem_u32(const void* p) {
    uint32_t a;
    asm("{ .reg .u64 t; cvta.to.shared.u64 t, %1; cvt.u32.u64 %0, t; }" : "=r"(a) : "l"(p));
    return a;
}
#define LDSM4(r0, r1, r2, r3, addr) \
    asm volatile("ldmatrix.sync.aligned.m8n8.x4.shared.b16 {%0,%1,%2,%3}, [%4];" \
        : "=r"(r0), "=r"(r1), "=r"(r2), "=r"(r3) : "r"(addr))
#define LDSM4T(r0, r1, r2, r3, addr) \
    asm volatile("ldmatrix.sync.aligned.m8n8.x4.trans.shared.b16 {%0,%1,%2,%3}, [%4];" \
        : "=r"(r0), "=r"(r1), "=r"(r2), "=r"(r3) : "r"(addr))

#define MMA16816(d, a0, a1, a2, a3, b0, b1) \
    asm volatile("mma.sync.aligned.m16n8k16.row.col.f32.bf16.bf16.f32 " \
        "{%0,%1,%2,%3}, {%4,%5,%6,%7}, {%8,%9}, {%0,%1,%2,%3};" \
        : "+f"((d)[0]), "+f"((d)[1]), "+f"((d)[2]), "+f"((d)[3]) \
        : "r"(a0), "r"(a1), "r"(a2), "r"(a3), "r"(b0), "r"(b1))

__device__ __forceinline__ uint32_t pack2(__nv_bfloat16 a, __nv_bfloat16 b) {
    return (uint32_t)__bfloat16_as_ushort(a) | ((uint32_t)__bfloat16_as_ushort(b) << 16);
}
__device__ __forceinline__ uint32_t pack2f(float a, float b) {
    return pack2(__float2bfloat16_rn(a), __float2bfloat16_rn(b));
}
__device__ __forceinline__ float bflo(uint32_t u) {
    return __bfloat162float(__ushort_as_bfloat16((unsigned short)(u & 0xFFFF)));
}
__device__ __forceinline__ float bfhi(uint32_t u) {
    return __bfloat162float(__ushort_as_bfloat16((unsigned short)(u >> 16)));
}

// ---------------------------------------------------------------------------
// K0: small precomputed operands
// ---------------------------------------------------------------------------
__global__ void k0_small(const float* __restrict__ dk)
{
    int t = threadIdx.x + blockIdx.x * blockDim.x;
    int stride = blockDim.x * gridDim.x;
    for (int i = t; i < 32 * 128; i += stride) {
        int m = i >> 7, w = i & 127;
        int ky = m >> 1, p = m & 1;
        float s, c;
        sincospif((float)(ky * w) * (1.0f / 64.0f), &s, &c);
        g_F2[i] = __float2bfloat16_rn(p == 0 ? c : -s);
    }
    for (int i = t; i < 64 * 256; i += stride) {
        int m = i >> 8, k = i & 255;
        int kxi = m >> 1, p = m & 1;
        int h = k >> 1, q = k & 1;
        int kx = (kxi < 16) ? kxi : (96 + kxi);
        float s, c;
        sincospif((float)(kx * h) * (1.0f / 64.0f), &s, &c);
        float v = (p == 0) ? (q == 0 ? c : s) : (q == 0 ? -s : c);
        g_G2[i] = __float2bfloat16_rn(v);
    }
    for (int i = t; i < 256 * 64; i += stride) {
        int m = i >> 6, kq = i & 63;
        int h = m >> 1, p = m & 1;
        int kxi = kq >> 1, q = kq & 1;
        int kx = (kxi < 16) ? kxi : (96 + kxi);
        float s, c;
        sincospif((float)(kx * h) * (1.0f / 64.0f), &s, &c);
        float v = (p == 0) ? (q == 0 ? c : -s) : (q == 0 ? s : c);
        g_Hinv[i] = __float2bfloat16_rn(v * (1.0f / 128.0f));
    }
    for (int i = t; i < WW * 32; i += stride) {
        int w = i >> 5, j = i & 31, ky = j & 15;
        float s, c;
        sincospif((float)(ky * w) * (1.0f / 64.0f), &s, &c);
        float sc = (ky == 0) ? (1.0f / 128.0f) : (2.0f / 128.0f);
        g_T[i] = __float2bfloat16_rn((j < 16) ? c * sc : -s * sc);
    }
    for (int i = t; i < CC * 128; i += stride) {
        int c = i >> 7, k = i & 127;
        int kk = k & 63;
        float v = dk[kk * 64 + c];
        __nv_bfloat16 hi = __float2bfloat16_rn(v);
        g_Bk[i] = (k < 64) ? hi : __float2bfloat16_rn(v - __bfloat162float(hi));
    }
}

// ---------------------------------------------------------------------------
// K1 (mma): per (b, 2h): P1[32 m=(ky,p), 64 c] = F2[32x128] @ x[128 w, 64 c]
// 2048 CTAs, ~45.5 KB smem -> 4+ CTAs/SM
// ---------------------------------------------------------------------------
#define K1_SA 136
#define K1_SX 72
#define K1_SMEM_A 0
#define K1_SMEM_X (32 * K1_SA * 2)                       // 8704
#define K1_SMEM_TOTAL (K1_SMEM_X + 2 * 128 * K1_SX * 2)  // 45568

__global__ __launch_bounds__(256) void k1_mma(const float* __restrict__ x)
{
    extern __shared__ char sm[];
    const uint32_t sbase = smem_u32(sm);
    const int b    = blockIdx.x >> 6;
    const int hg   = blockIdx.x & 63;    // pair of h
    const int t    = threadIdx.x;
    const int warp = t >> 5;
    const int lane = t & 31;

    {
        const uint32_t* src = (const uint32_t*)g_F2;
        for (int i = t; i < 32 * 64; i += 256) {
            int m = i >> 6, kp = i & 63;
            *(uint32_t*)(sm + K1_SMEM_A + m * K1_SA * 2 + kp * 4) = src[i];
        }
    }
    {
        const float4* xin = (const float4*)(x + ((size_t)(b * HH + hg * 2)) * WW * CC);
        for (int i = t; i < 2 * 128 * 16; i += 256) {
            float4 v = xin[i];
            int hl = i >> 11, w = (i >> 4) & 127, c4 = i & 15;
            uint32_t u0 = pack2f(v.x, v.y);
            uint32_t u1 = pack2f(v.z, v.w);
            *(uint2*)(sm + K1_SMEM_X + ((hl * 128 + w) * K1_SX + c4 * 4) * 2) = make_uint2(u0, u1);
        }
    }
    __syncthreads();

    const int hl = warp >> 2, nq = warp & 3;   // hl: which h; nq: n quarter (16 cols)
    const uint32_t Ab = sbase + K1_SMEM_A;
    const uint32_t Xb = sbase + K1_SMEM_X + hl * 128 * K1_SX * 2;

    float acc[2][2][4];
    #pragma unroll
    for (int mt = 0; mt < 2; mt++)
        #pragma unroll
        for (int nt = 0; nt < 2; nt++)
            #pragma unroll
            for (int q = 0; q < 4; q++) acc[mt][nt][q] = 0.f;

    const int arow = lane & 15;
    const int acol = (lane >> 4) * 8;
    const int brow = (lane & 7) + ((lane >> 3) & 1) * 8;
    const int bcol = (lane >> 4) * 8;

    #pragma unroll
    for (int ks = 0; ks < 8; ks++) {
        uint32_t a[2][4];
        #pragma unroll
        for (int mt = 0; mt < 2; mt++) {
            uint32_t addr = Ab + (uint32_t)((mt * 16 + arow) * K1_SA + ks * 16 + acol) * 2;
            LDSM4(a[mt][0], a[mt][1], a[mt][2], a[mt][3], addr);
        }
        uint32_t b0, b1, b2, b3;
        uint32_t addr = Xb + (uint32_t)((ks * 16 + brow) * K1_SX + nq * 16 + bcol) * 2;
        LDSM4T(b0, b1, b2, b3, addr);
        #pragma unroll
        for (int mt = 0; mt < 2; mt++) {
            MMA16816(acc[mt][0], a[mt][0], a[mt][1], a[mt][2], a[mt][3], b0, b1);
            MMA16816(acc[mt][1], a[mt][0], a[mt][1], a[mt][2], a[mt][3], b2, b3);
        }
    }

    // stage accumulators to smem [64 rows = (ky,hl,p)][72], then coalesced write
    __syncthreads();
    __nv_bfloat16* stg = (__nv_bfloat16*)(sm + K1_SMEM_X);
    #pragma unroll
    for (int mt = 0; mt < 2; mt++)
        #pragma unroll
        for (int nt = 0; nt < 2; nt++)
            #pragma unroll
            for (int half = 0; half < 2; half++) {
                int m = mt * 16 + (lane >> 2) + half * 8;
                int ky = m >> 1, p = m & 1;
                int c = nq * 16 + nt * 8 + 2 * (lane & 3);
                int sr = ky * 4 + hl * 2 + p;
                *(uint32_t*)(stg + sr * 72 + c) =
                    pack2f(acc[mt][nt][half * 2], acc[mt][nt][half * 2 + 1]);
            }
    __syncthreads();
    {
        int sr = t >> 2, seg = t & 3;
        int ky = sr >> 2, hl2 = (sr >> 1) & 1, p = sr & 1;
        size_t row = (((size_t)(b * 16 + ky)) * 256 + (hg * 2 + hl2) * 2 + p) * 64 + seg * 16;
        const uint4* src = (const uint4*)(stg + sr * 72 + seg * 16);
        uint4* dst = (uint4*)(g_P1b + row);
        dst[0] = src[0]; dst[1] = src[1];
    }
}

// ---------------------------------------------------------------------------
// K2 (mma): per (b,ky): X[64 m=(kxi,p), 64 c] = G2[64x256] @ P1b[256,64]
// ---------------------------------------------------------------------------
#define K2_SA 264
#define K2_SMEM_A 0
#define K2_SMEM_B (64 * K2_SA * 2)
#define K2_SMEM_TOTAL (K2_SMEM_B + 256 * K1_SX * 2)

__global__ __launch_bounds__(256) void k2_mma()
{
    extern __shared__ char sm[];
    const uint32_t sbase = smem_u32(sm);
    const int b    = blockIdx.x >> 4;
    const int ky   = blockIdx.x & 15;
    const int t    = threadIdx.x;
    const int warp = t >> 5;
    const int lane = t & 31;

    {
        const uint32_t* ga = (const uint32_t*)g_G2;
        for (int i = t; i < 64 * 128; i += 256) {
            int m = i >> 7, kp = i & 127;
            *(uint32_t*)(sm + K2_SMEM_A + (m * K2_SA + kp * 2) * 2) = ga[i];
        }
        const uint32_t* gb = (const uint32_t*)(g_P1b + ((size_t)(b * 16 + ky)) * 256 * 64);
        for (int i = t; i < 256 * 32; i += 256) {
            int r = i >> 5, cp = i & 31;
            *(uint32_t*)(sm + K2_SMEM_B + (r * K1_SX + cp * 2) * 2) = gb[i];
        }
    }
    __syncthreads();

    const int mi = warp >> 1, nh = warp & 1;
    float acc[4][4];
    #pragma unroll
    for (int nt = 0; nt < 4; nt++)
        #pragma unroll
        for (int q = 0; q < 4; q++) acc[nt][q] = 0.f;

    const int arow = lane & 15;
    const int acol = (lane >> 4) * 8;
    const int brow = (lane & 7) + ((lane >> 3) & 1) * 8;
    const int bcol = (lane >> 4) * 8;

    #pragma unroll
    for (int ks = 0; ks < 16; ks++) {
        uint32_t a0, a1, a2, a3;
        uint32_t aaddr = sbase + K2_SMEM_A + (uint32_t)((mi * 16 + arow) * K2_SA + ks * 16 + acol) * 2;
        LDSM4(a0, a1, a2, a3, aaddr);
        #pragma unroll
        for (int np = 0; np < 2; np++) {
            uint32_t b0, b1, b2, b3;
            uint32_t baddr = sbase + K2_SMEM_B
                + (uint32_t)((ks * 16 + brow) * K1_SX + nh * 32 + np * 16 + bcol) * 2;
            LDSM4T(b0, b1, b2, b3, baddr);
            MMA16816(acc[np * 2],     a0, a1, a2, a3, b0, b1);
            MMA16816(acc[np * 2 + 1], a0, a1, a2, a3, b2, b3);
        }
    }

    __syncthreads();
    __nv_bfloat16* stg = (__nv_bfloat16*)sm;   // [64 m][72]
    #pragma unroll
    for (int nt = 0; nt < 4; nt++)
        #pragma unroll
        for (int half = 0; half < 2; half++) {
            int m = mi * 16 + (lane >> 2) + half * 8;
            int c = nh * 32 + nt * 8 + 2 * (lane & 3);
            *(uint32_t*)(stg + m * 72 + c) = pack2f(acc[nt][half * 2], acc[nt][half * 2 + 1]);
        }
    __syncthreads();
    {
        int kxi = t >> 3, seg = t & 7;
        uint32_t vals[8];
        #pragma unroll
        for (int u = 0; u < 8; u++) {
            int j0 = seg * 16 + 2 * u;
            __nv_bfloat16 v0 = stg[(2 * kxi + (j0 & 1)) * 72 + (j0 >> 1)];
            __nv_bfloat16 v1 = stg[(2 * kxi + ((j0 + 1) & 1)) * 72 + ((j0 + 1) >> 1)];
            vals[u] = pack2(v0, v1);
        }
        uint4* dst = (uint4*)(g_X2 + ((size_t)(kxi * 16 + ky) * 32 + b) * 128 + seg * 16);
        dst[0] = make_uint4(vals[0], vals[1], vals[2], vals[3]);
        dst[1] = make_uint4(vals[4], vals[5], vals[6], vals[7]);
    }
}

// ---------------------------------------------------------------------------
// K3 (mma): per (kxi,ky): Y[32 b, 128 (o,p)] = X2[32x128] @ W2[128x128]
// ---------------------------------------------------------------------------
__global__ __launch_bounds__(256) void k3_mma(const float* __restrict__ w1r,
                                              const float* __restrict__ w1i,
                                              const float* __restrict__ w2r,
                                              const float* __restrict__ w2i)
{
    __shared__ __nv_bfloat16 sA[32 * 136];
    __shared__ __nv_bfloat16 sB[128 * 136];
    const int kq   = blockIdx.x;             // kxi*16+ky
    const int kxi  = kq >> 4, ky = kq & 15;
    const int t    = threadIdx.x;
    const int warp = t >> 5;
    const int lane = t & 31;

    {
        const uint32_t* ax = (const uint32_t*)(g_X2 + (size_t)kq * 32 * 128);
        for (int i = t; i < 32 * 64; i += 256) {
            int r = i >> 6, c32 = i & 63;
            *(uint32_t*)(sA + r * 136 + c32 * 2) = ax[i];
        }
        const float* wr;
        const float* wi;
        if (kxi < 16) { size_t off = (size_t)(kxi * 16 + ky) * 4096; wr = w1r + off; wi = w1i + off; }
        else          { size_t off = (size_t)((kxi - 16) * 16 + ky) * 4096; wr = w2r + off; wi = w2i + off; }
        const int ii = t >> 2;
        const int o0 = (t & 3) * 16;
        #pragma unroll
        for (int u = 0; u < 8; u++) {
            int o = o0 + 2 * u;
            float2 r2 = *(const float2*)(wr + ii * 64 + o);
            float2 i2 = *(const float2*)(wi + ii * 64 + o);
            *(uint2*)(sB + (2 * ii) * 136 + 2 * o) =
                make_uint2(pack2f(r2.x, i2.x), pack2f(r2.y, i2.y));
            *(uint2*)(sB + (2 * ii + 1) * 136 + 2 * o) =
                make_uint2(pack2f(-i2.x, r2.x), pack2f(-i2.y, r2.y));
        }
    }
    __syncthreads();

    const uint32_t sAb = smem_u32(sA);
    const uint32_t sBb = smem_u32(sB);
    float acc[2][2][4];
    #pragma unroll
    for (int mt = 0; mt < 2; mt++)
        #pragma unroll
        for (int g = 0; g < 2; g++)
            #pragma unroll
            for (int q = 0; q < 4; q++) acc[mt][g][q] = 0.f;

    const int arow = lane & 15;
    const int acol = (lane >> 4) * 8;
    const int bkr  = (lane & 7) + ((lane >> 3) & 1) * 8;
    const int bcol = (lane >> 4) * 8;

    #pragma unroll
    for (int ks = 0; ks < 8; ks++) {
        uint32_t a[2][4];
        #pragma unroll
        for (int mt = 0; mt < 2; mt++)
            LDSM4(a[mt][0], a[mt][1], a[mt][2], a[mt][3],
                  sAb + (uint32_t)((mt * 16 + arow) * 136 + ks * 16 + acol) * 2);
        uint32_t b0, b1, b2, b3;
        LDSM4T(b0, b1, b2, b3,
               sBb + (uint32_t)((ks * 16 + bkr) * 136 + warp * 16 + bcol) * 2);
        #pragma unroll
        for (int mt = 0; mt < 2; mt++) {
            MMA16816(acc[mt][0], a[mt][0], a[mt][1], a[mt][2], a[mt][3], b0, b1);
            MMA16816(acc[mt][1], a[mt][0], a[mt][1], a[mt][2], a[mt][3], b2, b3);
        }
    }

    __syncthreads();
    __nv_bfloat16* stg = sA;
    #pragma unroll
    for (int mt = 0; mt < 2; mt++)
        #pragma unroll
        for (int g = 0; g < 2; g++)
            #pragma unroll
            for (int half = 0; half < 2; half++) {
                int bi = mt * 16 + (lane >> 2) + half * 8;
                int n  = warp * 16 + g * 8 + 2 * (lane & 3);
                int o  = n >> 1;
                stg[bi * 136 + o]      = __float2bfloat16_rn(acc[mt][g][half * 2]);
                stg[bi * 136 + 64 + o] = __float2bfloat16_rn(acc[mt][g][half * 2 + 1]);
            }
    __syncthreads();
    {
        int b2 = t >> 3, seg = t & 7;
        const uint4* src = (const uint4*)(stg + b2 * 136 + seg * 16);
        uint4* dst = (uint4*)(g_Y2 + (((size_t)(b2 * 16 + ky)) * 64 + kxi * 2) * 64 + seg * 16);
        dst[0] = src[0]; dst[1] = src[1];
    }
}

// ---------------------------------------------------------------------------
// K4 (mma): per (b,ky): Z[256 (h,p), 64 c] = Hinv[256x64] @ Y2[64x64]
// ---------------------------------------------------------------------------
__global__ __launch_bounds__(256) void k4_mma()
{
    __shared__ __nv_bfloat16 sA[256 * 72];
    __shared__ __nv_bfloat16 sB[64 * 72];
    const int b    = blockIdx.x >> 4;
    const int ky   = blockIdx.x & 15;
    const int t    = threadIdx.x;
    const int warp = t >> 5;
    const int lane = t & 31;

    {
        const uint32_t* ah = (const uint32_t*)g_Hinv;
        for (int i = t; i < 256 * 32; i += 256) {
            int r = i >> 5, c32 = i & 31;
            *(uint32_t*)(sA + r * 72 + c32 * 2) = ah[i];
        }
        const uint32_t* by = (const uint32_t*)(g_Y2 + ((size_t)b * 16 + ky) * 64 * 64);
        for (int i = t; i < 64 * 32; i += 256) {
            int r = i >> 5, c32 = i & 31;
            *(uint32_t*)(sB + r * 72 + c32 * 2) = by[i];
        }
    }
    __syncthreads();

    const uint32_t sAb = smem_u32(sA);
    const uint32_t sBb = smem_u32(sB);
    const int wm = warp >> 1, wn = warp & 1;

    float acc[4][4][4];
    #pragma unroll
    for (int mt = 0; mt < 4; mt++)
        #pragma unroll
        for (int g = 0; g < 4; g++)
            #pragma unroll
            for (int q = 0; q < 4; q++) acc[mt][g][q] = 0.f;

    const int arow = lane & 15;
    const int acol = (lane >> 4) * 8;
    const int bkr  = (lane & 7) + ((lane >> 3) & 1) * 8;
    const int bcol = (lane >> 4) * 8;

    #pragma unroll
    for (int ks = 0; ks < 4; ks++) {
        uint32_t a[4][4];
        #pragma unroll
        for (int mt = 0; mt < 4; mt++)
            LDSM4(a[mt][0], a[mt][1], a[mt][2], a[mt][3],
                  sAb + (uint32_t)((wm * 64 + mt * 16 + arow) * 72 + ks * 16 + acol) * 2);
        #pragma unroll
        for (int np = 0; np < 2; np++) {
            uint32_t b0, b1, b2, b3;
            LDSM4T(b0, b1, b2, b3,
                   sBb + (uint32_t)((ks * 16 + bkr) * 72 + wn * 32 + np * 16 + bcol) * 2);
            #pragma unroll
            for (int mt = 0; mt < 4; mt++) {
                MMA16816(acc[mt][np * 2],     a[mt][0], a[mt][1], a[mt][2], a[mt][3], b0, b1);
                MMA16816(acc[mt][np * 2 + 1], a[mt][0], a[mt][1], a[mt][2], a[mt][3], b2, b3);
            }
        }
    }

    #pragma unroll
    for (int mt = 0; mt < 4; mt++)
        #pragma unroll
        for (int g = 0; g < 4; g++)
            #pragma unroll
            for (int half = 0; half < 2; half++) {
                int m = wm * 64 + mt * 16 + (lane >> 2) + half * 8;
                int h = m >> 1, p = m & 1;
                int n = wn * 32 + g * 8 + 2 * (lane & 3);
                size_t addr = (((size_t)b * 32 + p * 16 + ky) * 128 + h) * 64 + n;
                *(uint32_t*)(g_Z2 + addr) = pack2f(acc[mt][g][half * 2], acc[mt][g][half * 2 + 1]);
            }
}

// ---------------------------------------------------------------------------
// K5: mma.sync bf16 GEMM; 2 CTAs per (b,h), 64 w-rows each
//   A[64 x 160] = [ x_hi | x_lo | T ], SA=168
//   B[64 x 128] = [ K_hi | K_lo ],      SB=136
//   Zb[32 j][64 c], SZ=72 (trans loads in pass 4)
// ---------------------------------------------------------------------------
#define SA 168
#define SB 136
#define SZ 72
#define K5_BIAS 0
#define K5_A    256
#define K5_B    (K5_A + 64 * SA * 2)      // 256 + 21504 = 21760
#define K5_ZB   (K5_B + 64 * SB * 2)      // 21760 + 17408 = 39168
#define K5_SMEM (K5_ZB + 32 * SZ * 2)     // 39168 + 4608 = 43776

__global__ __launch_bounds__(256) void k5_mma(const float* __restrict__ x,
                                              const float* __restrict__ bias,
                                              float* __restrict__ out)
{
    extern __shared__ char smem[];
    const uint32_t sbase = smem_u32(smem);
    const int bh   = blockIdx.x >> 1;
    const int mh   = blockIdx.x & 1;       // which 64-row half
    const int t    = threadIdx.x;
    const int warp = t >> 5;
    const int lane = t & 31;

    // ---- A fill: x_hi (0..63), x_lo (64..127) for rows mh*64.. ----
    {
        const int w  = t >> 2;             // 0..63 local row
        const int c0 = (t & 3) * 16;
        const float4* xr4 = (const float4*)(x + (size_t)bh * 8192
                                            + (size_t)(mh * 64 + w) * 64 + c0);
        #pragma unroll
        for (int q = 0; q < 4; q++) {
            float4 v = xr4[q];
            __nv_bfloat16 h0 = __float2bfloat16_rn(v.x), h1 = __float2bfloat16_rn(v.y);
            __nv_bfloat16 h2 = __float2bfloat16_rn(v.z), h3 = __float2bfloat16_rn(v.w);
            uint32_t uhA = pack2(h0, h1), uhB = pack2(h2, h3);
            uint32_t ulA = pack2(__float2bfloat16_rn(v.x - __bfloat162float(h0)),
                                 __float2bfloat16_rn(v.y - __bfloat162float(h1)));
            uint32_t ulB = pack2(__float2bfloat16_rn(v.z - __bfloat162float(h2)),
                                 __float2bfloat16_rn(v.w - __bfloat162float(h3)));
            *(uint2*)(smem + K5_A + (w * SA + c0 + q * 4) * 2)      = make_uint2(uhA, uhB);
            *(uint2*)(smem + K5_A + (w * SA + 64 + c0 + q * 4) * 2) = make_uint2(ulA, ulB);
        }
    }
    // ---- A fill: T block (cols 128..159), global row mh*64+w ----
    if (t < 64) {
        const uint4* ts = (const uint4*)(g_T + (mh * 64 + t) * 32);
        #pragma unroll
        for (int ch = 0; ch < 4; ch++)
            *(uint4*)(smem + K5_A + (t * SA + 128 + ch * 8) * 2) = ts[ch];
    }
    // ---- B fill: K_hi | K_lo ----
    {
        const int c = t >> 2;
        const int q4 = t & 3;
        const uint4* src = (const uint4*)(g_Bk + c * 128 + q4 * 32);
        uint4* dst = (uint4*)(smem + K5_B + (c * SB + q4 * 32) * 2);
        dst[0] = src[0]; dst[1] = src[1]; dst[2] = src[2]; dst[3] = src[3];
    }
    // ---- Zb fill ----
    {
        const int b = bh >> 7, h = bh & 127;
        const int j = t >> 3, seg = t & 7;
        const uint4* src = (const uint4*)(g_Z2 + (((size_t)b * 32 + j) * 128 + h) * 64 + seg * 8);
        *(uint4*)(smem + K5_ZB + (j * SZ + seg * 8) * 2) = src[0];
    }
    if (t < 64) ((float*)(smem + K5_BIAS))[t] = bias[t];

    __syncthreads();

    // warps: wm = m-tile (rows wm*16..+15), wn = n-half (cols wn*32..+31)
    const int wm = warp >> 1, wn = warp & 1;
    float acc[4][4];
    #pragma unroll
    for (int nt = 0; nt < 4; nt++) {
        acc[nt][0] = 0.f; acc[nt][1] = 0.f; acc[nt][2] = 0.f; acc[nt][3] = 0.f;
    }

    const int arow  = wm * 16 + (lane & 7) + ((lane >> 3) & 1) * 8;
    const int akoff = (lane >> 4) * 8;
    const int brow  = (lane & 7) + (lane >> 4) * 8;
    const int bkoff = ((lane >> 3) & 1) * 8;
    const int zrow  = (lane & 7) + ((lane >> 3) & 1) * 8;
    const int zcol  = (lane >> 4) * 8;

    const int passes[3][2] = { {0, 0}, {0, 64}, {64, 0} };
    #pragma unroll
    for (int p = 0; p < 3; p++) {
        const int kA = passes[p][0], kB = passes[p][1];
        #pragma unroll
        for (int ks = 0; ks < 4; ks++) {
            uint32_t a0, a1, a2, a3;
            uint32_t aaddr = sbase + K5_A + (uint32_t)(arow * SA + kA + ks * 16 + akoff) * 2;
            LDSM4(a0, a1, a2, a3, aaddr);
            #pragma unroll
            for (int nt2 = 0; nt2 < 2; nt2++) {
                uint32_t b0, b1, b2, b3;
                uint32_t baddr = sbase + K5_B
                    + (uint32_t)((wn * 32 + nt2 * 16 + brow) * SB + kB + ks * 16 + bkoff) * 2;
                LDSM4(b0, b1, b2, b3, baddr);
                MMA16816(acc[2 * nt2],     a0, a1, a2, a3, b0, b1);
                MMA16816(acc[2 * nt2 + 1], a0, a1, a2, a3, b2, b3);
            }
        }
    }
    // pass 3: T x Z (trans loads)
    #pragma unroll
    for (int ks = 0; ks < 2; ks++) {
        uint32_t a0, a1, a2, a3;
        uint32_t aaddr = sbase + K5_A + (uint32_t)(arow * SA + 128 + ks * 16 + akoff) * 2;
        LDSM4(a0, a1, a2, a3, aaddr);
        #pragma unroll
        for (int nt2 = 0; nt2 < 2; nt2++) {
            uint32_t b0, b1, b2, b3;
            uint32_t baddr = sbase + K5_ZB
                + (uint32_t)((ks * 16 + zrow) * SZ + wn * 32 + nt2 * 16 + zcol) * 2;
            LDSM4T(b0, b1, b2, b3, baddr);
            MMA16816(acc[2 * nt2],     a0, a1, a2, a3, b0, b1);
            MMA16816(acc[2 * nt2 + 1], a0, a1, a2, a3, b2, b3);
        }
    }

    const int r0 = wm * 16 + (lane >> 2);
    const float* bs = (const float*)(smem + K5_BIAS);
    #pragma unroll
    for (int half = 0; half < 2; half++) {
        const int r = r0 + half * 8;
        float* orow = out + (size_t)bh * 8192 + (size_t)(mh * 64 + r) * 64;
        #pragma unroll
        for (int nt = 0; nt < 4; nt++) {
            const int c = wn * 32 + nt * 8 + 2 * (lane & 3);
            uint32_t hp = *(const uint32_t*)(smem + K5_A + (r * SA + c) * 2);
            uint32_t lp = *(const uint32_t*)(smem + K5_A + (r * SA + 64 + c) * 2);
            float res0 = bflo(hp) + bflo(lp);
            float res1 = bfhi(hp) + bfhi(lp);
            float s0 = acc[nt][half * 2 + 0] + res0 + bs[c];
            float s1 = acc[nt][half * 2 + 1] + res1 + bs[c + 1];
            float u0 = 0.7978845608028654f * (s0 + 0.044715f * s0 * s0 * s0);
            float u1 = 0.7978845608028654f * (s1 + 0.044715f * s1 * s1 * s1);
            float g0 = s0 * __frcp_rn(1.0f + __expf(-2.0f * u0));
            float g1 = s1 * __frcp_rn(1.0f + __expf(-2.0f * u1));
            *(float2*)(orow + c) = make_float2(g0, g1);
        }
    }
}

// ---------------------------------------------------------------------------
// Launch
// ---------------------------------------------------------------------------
extern "C" void kernel_launch(void* const* d_in, const int* in_sizes, int n_in,
                              void* d_out, int out_size)
{
    const float* x   = (const float*)d_in[0];
    const float* w1r = (const float*)d_in[1];
    const float* w1i = (const float*)d_in[2];
    const float* w2r = (const float*)d_in[3];
    const float* w2i = (const float*)d_in[4];
    const float* dk  = (const float*)d_in[5];
    const float* db  = (const float*)d_in[6];
    float* out = (float*)d_out;

    static int configured = 0;
    if (!configured) {
        cudaFuncSetAttribute(k1_mma, cudaFuncAttributeMaxDynamicSharedMemorySize, K1_SMEM_TOTAL);
        cudaFuncSetAttribute(k2_mma, cudaFuncAttributeMaxDynamicSharedMemorySize, K2_SMEM_TOTAL);
        cudaFuncSetAttribute(k5_mma, cudaFuncAttributeMaxDynamicSharedMemorySize, K5_SMEM);
        configured = 1;
    }

    k0_small<<<48, 256>>>(dk);
    k1_mma <<<BB * 64, 256, K1_SMEM_TOTAL>>>(x);
    k2_mma <<<BB * MY, 256, K2_SMEM_TOTAL>>>();
    k3_mma <<<512, 256>>>(w1r, w1i, w2r, w2i);
    k4_mma <<<BB * MY, 256>>>();
    k5_mma <<<BB * HH * 2, 256, K5_SMEM>>>(x, db, out);
}